// round 1
// baseline (speedup 1.0000x reference)
#include <cuda_runtime.h>

#define NN 100000
#define NE 300000
#define HID 256

// ---- scratch (static device globals; allocation-free) ----
__device__ float g_h0[NN * HID];
__device__ float g_h1[NN * HID];
__device__ float g_agg[NN * HID];
__device__ int   g_atype[NN];
__device__ int   g_pv[NN];
__device__ float g_deg[NN];
__device__ float g_tlogits[11 * 8];
__device__ int   g_tpv[11];

// ============================================================
// Per-atom-type valence MLP: only 11 distinct types exist.
// ============================================================
__global__ void k_type_pred(const float* __restrict__ atom_emb,
                            const float* __restrict__ w1, const float* __restrict__ b1,
                            const float* __restrict__ w2, const float* __restrict__ b2)
{
    int t = threadIdx.x;
    if (t >= 11) return;
    float z[32];
    for (int j = 0; j < 32; j++) {
        float s = b1[j];
        for (int k = 0; k < 64; k++) s += atom_emb[t * 64 + k] * w1[k * 32 + j];
        z[j] = fmaxf(s, 0.f);
    }
    float best = -1e30f; int bi = 0;
    for (int j = 0; j < 8; j++) {
        float s = b2[j];
        for (int k = 0; k < 32; k++) s += z[k] * w2[k * 8 + j];
        g_tlogits[t * 8 + j] = s;
        if (s > best) { best = s; bi = j; }   // first-max == jnp.argmax
    }
    g_tpv[t] = bi + 1;
}

// ============================================================
// Node init: gather per-type results, build h0 = [ae | onehot(pv-1) | 0...]
// one warp per node (coalesced row writes)
// ============================================================
__global__ void k_node_init(const float* __restrict__ x,
                            const float* __restrict__ atom_emb,
                            float* __restrict__ out_vlog)
{
    int gid = blockIdx.x * blockDim.x + threadIdx.x;
    int n = gid >> 5, lane = gid & 31;
    if (n >= NN) return;
    int at = (int)x[(size_t)n * 16];
    at = min(max(at, 0), 10);
    int pv = g_tpv[at];
    if (lane == 0) { g_atype[n] = at; g_pv[n] = pv; g_deg[n] = 0.f; }
    if (lane < 8) out_vlog[(size_t)n * 8 + lane] = g_tlogits[at * 8 + lane];
#pragma unroll
    for (int r = 0; r < 8; r++) {
        int c = lane + 32 * r;
        float v;
        if (c < 64)      v = atom_emb[at * 64 + c];
        else if (c < 72) v = (c - 64 == pv - 1) ? 1.f : 0.f;
        else             v = 0.f;
        g_h0[(size_t)n * HID + c] = v;
    }
}

__global__ void k_degree(const int* __restrict__ edge_index)
{
    int e = blockIdx.x * blockDim.x + threadIdx.x;
    if (e < NE) atomicAdd(&g_deg[edge_index[e]], 1.f);
}

__global__ void k_zero_agg()
{
    int i = blockIdx.x * blockDim.x + threadIdx.x;  // 6,400,000 float4s exactly
    ((float4*)g_agg)[i] = make_float4(0.f, 0.f, 0.f, 0.f);
}

// ============================================================
// msg GEMM: [32 edges x 256 out], K=320 (h[col] 256 + bond_emb 64),
// relu + bias, scatter-add into g_agg via atomics.
// ============================================================
__global__ __launch_bounds__(256) void k_msg(int ping,
        const float* __restrict__ wmsg, const float* __restrict__ bmsg,
        const float* __restrict__ bond_emb, const float* __restrict__ edge_attr,
        const int* __restrict__ edge_index)
{
    const float* __restrict__ hin = ping ? g_h1 : g_h0;
    __shared__ float As[32][33];
    __shared__ float Ws[32][256];
    __shared__ int s_col[32], s_row[32], s_bt[32];
    int tid = threadIdx.x;
    int eb = blockIdx.x * 32;
    if (tid < 32) {
        int e = eb + tid;
        s_row[tid] = edge_index[e];
        s_col[tid] = edge_index[NE + e];
        int bt = (int)edge_attr[(size_t)e * 4];
        s_bt[tid] = min(max(bt, 0), 4);
    }
    __syncthreads();
    float acc[4][8];
#pragma unroll
    for (int i = 0; i < 4; i++)
#pragma unroll
        for (int j = 0; j < 8; j++) acc[i][j] = 0.f;
    const int tx = tid & 31, ty = tid >> 5;
    for (int kt = 0; kt < 10; kt++) {
        int k0 = kt * 32;
#pragma unroll
        for (int i = 0; i < 4; i++) {
            int q = tid + 256 * i;
            int e = q >> 5, k = q & 31;
            int kk = k0 + k;
            float v;
            if (kk < 256) v = hin[(size_t)s_col[e] * HID + kk];
            else          v = bond_emb[s_bt[e] * 64 + (kk - 256)];
            As[e][k] = v;
        }
#pragma unroll
        for (int i = 0; i < 32; i++) {
            int q = tid + 256 * i;
            int k = q >> 8, o = q & 255;
            Ws[k][o] = wmsg[(size_t)(k0 + k) * HID + o];
        }
        __syncthreads();
#pragma unroll
        for (int kk = 0; kk < 32; kk++) {
            float a[4];
#pragma unroll
            for (int i = 0; i < 4; i++) a[i] = As[ty * 4 + i][kk];
            float4 w0 = *(const float4*)&Ws[kk][tx * 8];
            float4 w1 = *(const float4*)&Ws[kk][tx * 8 + 4];
#pragma unroll
            for (int i = 0; i < 4; i++) {
                acc[i][0] += a[i] * w0.x; acc[i][1] += a[i] * w0.y;
                acc[i][2] += a[i] * w0.z; acc[i][3] += a[i] * w0.w;
                acc[i][4] += a[i] * w1.x; acc[i][5] += a[i] * w1.y;
                acc[i][6] += a[i] * w1.z; acc[i][7] += a[i] * w1.w;
            }
        }
        __syncthreads();
    }
#pragma unroll
    for (int i = 0; i < 4; i++) {
        int r = s_row[ty * 4 + i];
#pragma unroll
        for (int j = 0; j < 8; j++) {
            int o = tx * 8 + j;
            float v = acc[i][j] + __ldg(&bmsg[o]);
            v = fmaxf(v, 0.f);
            atomicAdd(&g_agg[(size_t)r * HID + o], v);
        }
    }
}

// ============================================================
// self GEMM: h_new = relu(h @ Wself + b + agg), [32 nodes x 256], K=256
// ============================================================
__global__ __launch_bounds__(256) void k_self(int ping,
        const float* __restrict__ wself, const float* __restrict__ bself)
{
    const float* __restrict__ hin  = ping ? g_h1 : g_h0;
    float* __restrict__ hout       = ping ? g_h0 : g_h1;
    __shared__ float As[32][33];
    __shared__ float Ws[32][256];
    int tid = threadIdx.x;
    int nb = blockIdx.x * 32;
    float acc[4][8];
#pragma unroll
    for (int i = 0; i < 4; i++)
#pragma unroll
        for (int j = 0; j < 8; j++) acc[i][j] = 0.f;
    const int tx = tid & 31, ty = tid >> 5;
    for (int kt = 0; kt < 8; kt++) {
        int k0 = kt * 32;
#pragma unroll
        for (int i = 0; i < 4; i++) {
            int q = tid + 256 * i;
            int e = q >> 5, k = q & 31;
            As[e][k] = hin[(size_t)(nb + e) * HID + k0 + k];
        }
#pragma unroll
        for (int i = 0; i < 32; i++) {
            int q = tid + 256 * i;
            int k = q >> 8, o = q & 255;
            Ws[k][o] = wself[(size_t)(k0 + k) * HID + o];
        }
        __syncthreads();
#pragma unroll
        for (int kk = 0; kk < 32; kk++) {
            float a[4];
#pragma unroll
            for (int i = 0; i < 4; i++) a[i] = As[ty * 4 + i][kk];
            float4 w0 = *(const float4*)&Ws[kk][tx * 8];
            float4 w1 = *(const float4*)&Ws[kk][tx * 8 + 4];
#pragma unroll
            for (int i = 0; i < 4; i++) {
                acc[i][0] += a[i] * w0.x; acc[i][1] += a[i] * w0.y;
                acc[i][2] += a[i] * w0.z; acc[i][3] += a[i] * w0.w;
                acc[i][4] += a[i] * w1.x; acc[i][5] += a[i] * w1.y;
                acc[i][6] += a[i] * w1.z; acc[i][7] += a[i] * w1.w;
            }
        }
        __syncthreads();
    }
#pragma unroll
    for (int i = 0; i < 4; i++) {
        int n = nb + ty * 4 + i;
        float4 g0 = *(const float4*)&g_agg[(size_t)n * HID + tx * 8];
        float4 g1 = *(const float4*)&g_agg[(size_t)n * HID + tx * 8 + 4];
        float4 r0, r1;
        r0.x = fmaxf(acc[i][0] + __ldg(&bself[tx * 8 + 0]) + g0.x, 0.f);
        r0.y = fmaxf(acc[i][1] + __ldg(&bself[tx * 8 + 1]) + g0.y, 0.f);
        r0.z = fmaxf(acc[i][2] + __ldg(&bself[tx * 8 + 2]) + g0.z, 0.f);
        r0.w = fmaxf(acc[i][3] + __ldg(&bself[tx * 8 + 3]) + g0.w, 0.f);
        r1.x = fmaxf(acc[i][4] + __ldg(&bself[tx * 8 + 4]) + g1.x, 0.f);
        r1.y = fmaxf(acc[i][5] + __ldg(&bself[tx * 8 + 5]) + g1.y, 0.f);
        r1.z = fmaxf(acc[i][6] + __ldg(&bself[tx * 8 + 6]) + g1.z, 0.f);
        r1.w = fmaxf(acc[i][7] + __ldg(&bself[tx * 8 + 7]) + g1.w, 0.f);
        *(float4*)&hout[(size_t)n * HID + tx * 8] = r0;
        *(float4*)&hout[(size_t)n * HID + tx * 8 + 4] = r1;
    }
}

// ============================================================
// Valence damping: h_final = h / (1 + relu(deg - pv)); writes h + violations
// ============================================================
__global__ void k_damp(float* __restrict__ out_h, float* __restrict__ out_viol)
{
    int idx = blockIdx.x * 256 + threadIdx.x;   // 6,400,000 float4s exactly
    int n = idx >> 6;
    float viol = fmaxf(g_deg[n] - (float)g_pv[n], 0.f);
    float s = 1.f / (1.f + viol);
    float4 v = ((const float4*)g_h1)[idx];
    v.x *= s; v.y *= s; v.z *= s; v.w *= s;
    ((float4*)out_h)[idx] = v;
    if (idx < NN)
        out_viol[idx] = fmaxf(g_deg[idx] - (float)g_pv[idx], 0.f);
}

// ============================================================
// Bond head: 3-layer MLP on [h[row]|h[col]|pv_r|pv_c] (K=514) + chem penalties
// ============================================================
__global__ __launch_bounds__(256) void k_bc(const float* __restrict__ hfin,
        const float* __restrict__ w1, const float* __restrict__ b1,
        const float* __restrict__ w2, const float* __restrict__ b2,
        const float* __restrict__ w3, const float* __restrict__ b3,
        const int* __restrict__ edge_index, float* __restrict__ out_bl)
{
    __shared__ float As[32][33];
    __shared__ float Ws[32][128];
    __shared__ float T1[32][129];
    __shared__ float T2[32][65];
    __shared__ int s_row[32], s_col[32], s_atr[32], s_atc[32];
    __shared__ float s_pvr[32], s_pvc[32];
    int tid = threadIdx.x;
    int eb = blockIdx.x * 32;
    if (tid < 32) {
        int e = eb + tid;
        int r = edge_index[e], c = edge_index[NE + e];
        s_row[tid] = r; s_col[tid] = c;
        s_pvr[tid] = (float)g_pv[r]; s_pvc[tid] = (float)g_pv[c];
        s_atr[tid] = g_atype[r];     s_atc[tid] = g_atype[c];
    }
    __syncthreads();

    // ---- stage 1: [32 x 128], K=512 tiled + pv rank-2 terms ----
    float acc[4][4];
#pragma unroll
    for (int i = 0; i < 4; i++)
#pragma unroll
        for (int j = 0; j < 4; j++) acc[i][j] = 0.f;
    const int tx = tid & 31, ty = tid >> 5;
    for (int kt = 0; kt < 16; kt++) {
        int k0 = kt * 32;
#pragma unroll
        for (int i = 0; i < 4; i++) {
            int q = tid + 256 * i;
            int e = q >> 5, k = q & 31;
            int kk = k0 + k;
            float v;
            if (kk < 256) v = hfin[(size_t)s_row[e] * HID + kk];
            else          v = hfin[(size_t)s_col[e] * HID + kk - 256];
            As[e][k] = v;
        }
#pragma unroll
        for (int i = 0; i < 16; i++) {
            int q = tid + 256 * i;
            int k = q >> 7, o = q & 127;
            Ws[k][o] = w1[(size_t)(k0 + k) * 128 + o];
        }
        __syncthreads();
#pragma unroll
        for (int kk = 0; kk < 32; kk++) {
            float a[4];
#pragma unroll
            for (int i = 0; i < 4; i++) a[i] = As[ty * 4 + i][kk];
            float4 w = *(const float4*)&Ws[kk][tx * 4];
#pragma unroll
            for (int i = 0; i < 4; i++) {
                acc[i][0] += a[i] * w.x; acc[i][1] += a[i] * w.y;
                acc[i][2] += a[i] * w.z; acc[i][3] += a[i] * w.w;
            }
        }
        __syncthreads();
    }
#pragma unroll
    for (int i = 0; i < 4; i++) {
        int e = ty * 4 + i;
#pragma unroll
        for (int j = 0; j < 4; j++) {
            int o = tx * 4 + j;
            float v = acc[i][j]
                    + s_pvr[e] * __ldg(&w1[512 * 128 + o])
                    + s_pvc[e] * __ldg(&w1[513 * 128 + o])
                    + __ldg(&b1[o]);
            T1[e][o] = fmaxf(v, 0.f);
        }
    }
    __syncthreads();

    // ---- stage 2: [32 x 64], K=128 (W2 staged through Ws in 32-chunks) ----
    float acc2[2][4];
#pragma unroll
    for (int i = 0; i < 2; i++)
#pragma unroll
        for (int j = 0; j < 4; j++) acc2[i][j] = 0.f;
    const int tx2 = tid & 15, ty2 = tid >> 4;
    for (int kt = 0; kt < 4; kt++) {
        int k0 = kt * 32;
#pragma unroll
        for (int i = 0; i < 8; i++) {
            int q = tid + 256 * i;
            int k = q >> 6, o = q & 63;
            Ws[k][o] = w2[(size_t)(k0 + k) * 64 + o];
        }
        __syncthreads();
#pragma unroll
        for (int kk = 0; kk < 32; kk++) {
            float a0 = T1[ty2 * 2][k0 + kk];
            float a1 = T1[ty2 * 2 + 1][k0 + kk];
            float4 w = *(const float4*)&Ws[kk][tx2 * 4];
            acc2[0][0] += a0 * w.x; acc2[0][1] += a0 * w.y;
            acc2[0][2] += a0 * w.z; acc2[0][3] += a0 * w.w;
            acc2[1][0] += a1 * w.x; acc2[1][1] += a1 * w.y;
            acc2[1][2] += a1 * w.z; acc2[1][3] += a1 * w.w;
        }
        __syncthreads();
    }
#pragma unroll
    for (int i = 0; i < 2; i++) {
        int e = ty2 * 2 + i;
#pragma unroll
        for (int j = 0; j < 4; j++) {
            int o = tx2 * 4 + j;
            T2[e][o] = fmaxf(acc2[i][j] + __ldg(&b2[o]), 0.f);
        }
    }
    __syncthreads();

    // ---- stage 3: [32 x 4], K=64, + vectorized chemical penalties ----
    if (tid < 128) {
        int e = tid >> 2, o = tid & 3;
        float s = __ldg(&b3[o]);
#pragma unroll
        for (int k = 0; k < 64; k++) s += T2[e][k] * __ldg(&w3[k * 4 + o]);
        int ar = s_atr[e], ac = s_atc[e];
        float pr = s_pvr[e], pc = s_pvc[e];
        bool hal = (ar == 4) || (ar == 5) || (ac == 4) || (ac == 5);
        bool l1 = (pr <= 1.f) || (pc <= 1.f);
        bool l2 = (pr <= 2.f) || (pc <= 2.f);
        float pen = 0.f;
        if (o >= 1) { if (hal) pen -= 100.f; if (l1) pen -= 50.f; }
        if (o == 2) { if (l2) pen -= 50.f; }
        out_bl[(size_t)(eb + e) * 4 + o] = s + pen;
    }
}

// ============================================================
// Chem head: relu(h @ w1 + b1) @ w2 + b2, [32 nodes], K=256 then K=128
// ============================================================
__global__ __launch_bounds__(256) void k_cp(const float* __restrict__ hfin,
        const float* __restrict__ w1, const float* __restrict__ b1,
        const float* __restrict__ w2, const float* __restrict__ b2,
        float* __restrict__ out_cp)
{
    __shared__ float As[32][33];
    __shared__ float Ws[32][128];
    __shared__ float T1[32][129];
    int tid = threadIdx.x;
    int nb = blockIdx.x * 32;
    float acc[4][4];
#pragma unroll
    for (int i = 0; i < 4; i++)
#pragma unroll
        for (int j = 0; j < 4; j++) acc[i][j] = 0.f;
    const int tx = tid & 31, ty = tid >> 5;
    for (int kt = 0; kt < 8; kt++) {
        int k0 = kt * 32;
#pragma unroll
        for (int i = 0; i < 4; i++) {
            int q = tid + 256 * i;
            int e = q >> 5, k = q & 31;
            As[e][k] = hfin[(size_t)(nb + e) * HID + k0 + k];
        }
#pragma unroll
        for (int i = 0; i < 16; i++) {
            int q = tid + 256 * i;
            int k = q >> 7, o = q & 127;
            Ws[k][o] = w1[(size_t)(k0 + k) * 128 + o];
        }
        __syncthreads();
#pragma unroll
        for (int kk = 0; kk < 32; kk++) {
            float a[4];
#pragma unroll
            for (int i = 0; i < 4; i++) a[i] = As[ty * 4 + i][kk];
            float4 w = *(const float4*)&Ws[kk][tx * 4];
#pragma unroll
            for (int i = 0; i < 4; i++) {
                acc[i][0] += a[i] * w.x; acc[i][1] += a[i] * w.y;
                acc[i][2] += a[i] * w.z; acc[i][3] += a[i] * w.w;
            }
        }
        __syncthreads();
    }
#pragma unroll
    for (int i = 0; i < 4; i++) {
        int e = ty * 4 + i;
#pragma unroll
        for (int j = 0; j < 4; j++) {
            int o = tx * 4 + j;
            T1[e][o] = fmaxf(acc[i][j] + __ldg(&b1[o]), 0.f);
        }
    }
    __syncthreads();

    // stage 2: [32 x 32], K=128
    float acc2[4] = {0.f, 0.f, 0.f, 0.f};
    const int tx2 = tid & 7, ty2 = tid >> 3;
    for (int kt = 0; kt < 4; kt++) {
        int k0 = kt * 32;
#pragma unroll
        for (int i = 0; i < 4; i++) {
            int q = tid + 256 * i;
            int k = q >> 5, o = q & 31;
            Ws[k][o] = w2[(size_t)(k0 + k) * 32 + o];
        }
        __syncthreads();
#pragma unroll
        for (int kk = 0; kk < 32; kk++) {
            float a = T1[ty2][k0 + kk];
            float4 w = *(const float4*)&Ws[kk][tx2 * 4];
            acc2[0] += a * w.x; acc2[1] += a * w.y;
            acc2[2] += a * w.z; acc2[3] += a * w.w;
        }
        __syncthreads();
    }
#pragma unroll
    for (int j = 0; j < 4; j++) {
        int o = tx2 * 4 + j;
        out_cp[(size_t)(nb + ty2) * 32 + o] = acc2[j] + __ldg(&b2[o]);
    }
}

// ============================================================
extern "C" void kernel_launch(void* const* d_in, const int* in_sizes, int n_in,
                              void* d_out, int out_size)
{
    (void)in_sizes; (void)n_in; (void)out_size;
    const float* x         = (const float*)d_in[0];
    const float* edge_attr = (const float*)d_in[1];
    const float* atom_emb  = (const float*)d_in[2];
    const float* bond_emb  = (const float*)d_in[3];
    const float* vp_w1     = (const float*)d_in[4];
    const float* vp_b1     = (const float*)d_in[5];
    const float* vp_w2     = (const float*)d_in[6];
    const float* vp_b2     = (const float*)d_in[7];
    const float* gnn_wself = (const float*)d_in[8];
    const float* gnn_bself = (const float*)d_in[9];
    const float* gnn_wmsg  = (const float*)d_in[10];
    const float* gnn_bmsg  = (const float*)d_in[11];
    const float* bc_w1     = (const float*)d_in[12];
    const float* bc_b1     = (const float*)d_in[13];
    const float* bc_w2     = (const float*)d_in[14];
    const float* bc_b2     = (const float*)d_in[15];
    const float* bc_w3     = (const float*)d_in[16];
    const float* bc_b3     = (const float*)d_in[17];
    const float* cp_w1     = (const float*)d_in[18];
    const float* cp_b1     = (const float*)d_in[19];
    const float* cp_w2     = (const float*)d_in[20];
    const float* cp_b2     = (const float*)d_in[21];
    const int* edge_index  = (const int*)d_in[22];

    float* out      = (float*)d_out;
    float* out_h    = out;                                 // [N,256]
    float* out_cp   = out_h   + (size_t)NN * HID;          // [N,32]
    float* out_vlog = out_cp  + (size_t)NN * 32;           // [N,8]
    float* out_bl   = out_vlog + (size_t)NN * 8;           // [E,4]
    float* out_viol = out_bl  + (size_t)NE * 4;            // [N]

    k_type_pred<<<1, 32>>>(atom_emb, vp_w1, vp_b1, vp_w2, vp_b2);
    k_node_init<<<(NN * 32 + 255) / 256, 256>>>(x, atom_emb, out_vlog);
    k_degree<<<(NE + 255) / 256, 256>>>(edge_index);

    int ping = 0;
    for (int l = 0; l < 3; l++) {
        k_zero_agg<<<(NN * HID / 4) / 256, 256>>>();
        k_msg<<<NE / 32, 256>>>(ping, gnn_wmsg + (size_t)l * 320 * HID,
                                gnn_bmsg + l * HID, bond_emb, edge_attr, edge_index);
        k_self<<<NN / 32, 256>>>(ping, gnn_wself + (size_t)l * HID * HID,
                                 gnn_bself + l * HID);
        ping ^= 1;
    }
    // after 3 layers (ping toggled 0->1->0->1), final h is in g_h1
    k_damp<<<(NN * HID / 4) / 256, 256>>>(out_h, out_viol);
    k_bc<<<NE / 32, 256>>>(out_h, bc_w1, bc_b1, bc_w2, bc_b2, bc_w3, bc_b3,
                           edge_index, out_bl);
    k_cp<<<NN / 32, 256>>>(out_h, cp_w1, cp_b1, cp_w2, cp_b2, out_cp);
}

// round 2
// speedup vs baseline: 3.1226x; 3.1226x over previous
#include <cuda_runtime.h>

#define NN 100000
#define NE 300000
#define HID 256

// ---- scratch (static device globals; allocation-free) ----
__device__ float g_h0[NN * HID];
__device__ float g_h1[NN * HID];
__device__ float g_agg[NN * HID];
__device__ int   g_atype[NN];
__device__ int   g_pv[NN];
__device__ float g_deg[NN];
__device__ float g_tlogits[11 * 8];
__device__ int   g_tpv[11];
__device__ float g_msgbias[3 * 5 * 256];   // folded bond-emb @ Wmsg[256:] + bmsg

__device__ __forceinline__ unsigned f2tf(float x) {
    unsigned r;
    asm("cvt.rna.tf32.f32 %0, %1;" : "=r"(r) : "f"(x));
    return __uint_as_float(r) == 0.f ? r : r;  // keep as bits
}
__device__ __forceinline__ float f2tff(float x) {
    unsigned r;
    asm("cvt.rna.tf32.f32 %0, %1;" : "=r"(r) : "f"(x));
    return __uint_as_float(r);
}

__device__ __forceinline__ void mma_tf32(float c[4],
    unsigned a0, unsigned a1, unsigned a2, unsigned a3,
    unsigned b0, unsigned b1)
{
    asm volatile(
        "mma.sync.aligned.m16n8k8.row.col.f32.tf32.tf32.f32 "
        "{%0,%1,%2,%3}, {%4,%5,%6,%7}, {%8,%9}, {%0,%1,%2,%3};"
        : "+f"(c[0]), "+f"(c[1]), "+f"(c[2]), "+f"(c[3])
        : "r"(a0), "r"(a1), "r"(a2), "r"(a3), "r"(b0), "r"(b1));
}

// ============================================================
// Per-atom-type valence MLP: only 11 distinct types exist.
// ============================================================
__global__ void k_type_pred(const float* __restrict__ atom_emb,
                            const float* __restrict__ w1, const float* __restrict__ b1,
                            const float* __restrict__ w2, const float* __restrict__ b2)
{
    int t = threadIdx.x;
    if (t >= 11) return;
    float z[32];
    for (int j = 0; j < 32; j++) {
        float s = b1[j];
        for (int k = 0; k < 64; k++) s += atom_emb[t * 64 + k] * w1[k * 32 + j];
        z[j] = fmaxf(s, 0.f);
    }
    float best = -1e30f; int bi = 0;
    for (int j = 0; j < 8; j++) {
        float s = b2[j];
        for (int k = 0; k < 32; k++) s += z[k] * w2[k * 8 + j];
        g_tlogits[t * 8 + j] = s;
        if (s > best) { best = s; bi = j; }
    }
    g_tpv[t] = bi + 1;
}

// ============================================================
// Fold bond embedding through Wmsg[256:320] into per-(layer,bondtype) bias.
// grid = 15 blocks (l*5+bt), block = 256 threads (one per out col)
// ============================================================
__global__ void k_fold(const float* __restrict__ wmsg_all,
                       const float* __restrict__ bmsg_all,
                       const float* __restrict__ bond_emb)
{
    int l = blockIdx.x / 5, bt = blockIdx.x % 5;
    int o = threadIdx.x;
    const float* w = wmsg_all + (size_t)l * 320 * HID;
    float s = bmsg_all[l * HID + o];
#pragma unroll 8
    for (int j = 0; j < 64; j++)
        s += bond_emb[bt * 64 + j] * w[(size_t)(256 + j) * HID + o];
    g_msgbias[(size_t)blockIdx.x * 256 + o] = s;
}

// ============================================================
// Node init: h0 = [ae | onehot(pv-1) | 0...], one warp per node
// ============================================================
__global__ void k_node_init(const float* __restrict__ x,
                            const float* __restrict__ atom_emb,
                            float* __restrict__ out_vlog)
{
    int gid = blockIdx.x * blockDim.x + threadIdx.x;
    int n = gid >> 5, lane = gid & 31;
    if (n >= NN) return;
    int at = (int)x[(size_t)n * 16];
    at = min(max(at, 0), 10);
    int pv = g_tpv[at];
    if (lane == 0) { g_atype[n] = at; g_pv[n] = pv; g_deg[n] = 0.f; }
    if (lane < 8) out_vlog[(size_t)n * 8 + lane] = g_tlogits[at * 8 + lane];
#pragma unroll
    for (int r = 0; r < 8; r++) {
        int c = lane + 32 * r;
        float v;
        if (c < 64)      v = atom_emb[at * 64 + c];
        else if (c < 72) v = (c - 64 == pv - 1) ? 1.f : 0.f;
        else             v = 0.f;
        g_h0[(size_t)n * HID + c] = v;
    }
}

__global__ void k_degree(const int* __restrict__ edge_index)
{
    int e = blockIdx.x * blockDim.x + threadIdx.x;
    if (e < NE) atomicAdd(&g_deg[edge_index[e]], 1.f);
}

__global__ void k_zero_agg()
{
    int i = blockIdx.x * blockDim.x + threadIdx.x;
    ((float4*)g_agg)[i] = make_float4(0.f, 0.f, 0.f, 0.f);
}

// ============================================================
// msg GEMM (tf32 MMA): [32 edges x 256], K = 32*ksteps over h[col],
// + per-bondtype folded bias, relu, atomic scatter into g_agg.
// 8 warps; warp w owns out cols [w*32, w*32+32).
// ============================================================
__global__ __launch_bounds__(256) void k_msg(int ping, int ksteps, int l,
        const float* __restrict__ wmsg,
        const float* __restrict__ edge_attr, const int* __restrict__ edge_index)
{
    const float* __restrict__ hin = ping ? g_h1 : g_h0;
    __shared__ float As[32][36];
    __shared__ float Ws[32][264];
    __shared__ int s_row[32], s_col[32], s_bt[32];
    int tid = threadIdx.x;
    int eb = blockIdx.x * 32;
    if (tid < 32) {
        int e = eb + tid;
        s_row[tid] = edge_index[e];
        s_col[tid] = edge_index[NE + e];
        s_bt[tid] = min(max((int)edge_attr[(size_t)e * 4], 0), 4);
    }
    __syncthreads();
    int warp = tid >> 5, lane = tid & 31;
    int n0 = warp * 32;
    float c[2][4][4];
#pragma unroll
    for (int m = 0; m < 2; m++)
#pragma unroll
        for (int n = 0; n < 4; n++)
#pragma unroll
            for (int j = 0; j < 4; j++) c[m][n][j] = 0.f;

    for (int kt = 0; kt < ksteps; kt++) {
        int k0 = kt * 32;
#pragma unroll
        for (int i = 0; i < 4; i++) {
            int q = tid + 256 * i;
            int e = q >> 5, k = q & 31;
            As[e][k] = f2tff(hin[(size_t)s_col[e] * HID + k0 + k]);
        }
#pragma unroll
        for (int i = 0; i < 32; i++) {
            int q = tid + 256 * i;
            int k = q >> 8, o = q & 255;
            Ws[k][o] = f2tff(wmsg[(size_t)(k0 + k) * HID + o]);
        }
        __syncthreads();
        int lr = lane >> 2, lc = lane & 3;
#pragma unroll
        for (int ks = 0; ks < 4; ks++) {
            int kk = ks * 8;
            unsigned a[2][4];
#pragma unroll
            for (int m = 0; m < 2; m++) {
                int r = m * 16 + lr;
                a[m][0] = __float_as_uint(As[r][kk + lc]);
                a[m][1] = __float_as_uint(As[r + 8][kk + lc]);
                a[m][2] = __float_as_uint(As[r][kk + 4 + lc]);
                a[m][3] = __float_as_uint(As[r + 8][kk + 4 + lc]);
            }
#pragma unroll
            for (int n = 0; n < 4; n++) {
                int nc = n0 + n * 8 + lr;
                unsigned b0 = __float_as_uint(Ws[kk + lc][nc]);
                unsigned b1 = __float_as_uint(Ws[kk + 4 + lc][nc]);
#pragma unroll
                for (int m = 0; m < 2; m++)
                    mma_tf32(c[m][n], a[m][0], a[m][1], a[m][2], a[m][3], b0, b1);
            }
        }
        __syncthreads();
    }
    // epilogue: bias (per bond type) + relu + atomic scatter
    const float* mb = g_msgbias + (size_t)l * 5 * 256;
    int g = lane >> 2, cc = 2 * (lane & 3);
#pragma unroll
    for (int m = 0; m < 2; m++) {
        int r0 = m * 16 + g, r1 = r0 + 8;
        int row0 = s_row[r0], row1 = s_row[r1];
        const float* mb0 = mb + s_bt[r0] * 256;
        const float* mb1 = mb + s_bt[r1] * 256;
#pragma unroll
        for (int n = 0; n < 4; n++) {
            int col = n0 + n * 8 + cc;
            float v0 = fmaxf(c[m][n][0] + mb0[col],     0.f);
            float v1 = fmaxf(c[m][n][1] + mb0[col + 1], 0.f);
            float v2 = fmaxf(c[m][n][2] + mb1[col],     0.f);
            float v3 = fmaxf(c[m][n][3] + mb1[col + 1], 0.f);
            atomicAdd(&g_agg[(size_t)row0 * HID + col],     v0);
            atomicAdd(&g_agg[(size_t)row0 * HID + col + 1], v1);
            atomicAdd(&g_agg[(size_t)row1 * HID + col],     v2);
            atomicAdd(&g_agg[(size_t)row1 * HID + col + 1], v3);
        }
    }
}

// ============================================================
// self GEMM (tf32 MMA): h_new = relu(h @ Wself + b + agg), [32 nodes x 256]
// ============================================================
__global__ __launch_bounds__(256) void k_self(int ping, int ksteps,
        const float* __restrict__ wself, const float* __restrict__ bself)
{
    const float* __restrict__ hin  = ping ? g_h1 : g_h0;
    float* __restrict__ hout       = ping ? g_h0 : g_h1;
    __shared__ float As[32][36];
    __shared__ float Ws[32][264];
    int tid = threadIdx.x;
    int nb = blockIdx.x * 32;
    int warp = tid >> 5, lane = tid & 31;
    int n0 = warp * 32;
    float c[2][4][4];
#pragma unroll
    for (int m = 0; m < 2; m++)
#pragma unroll
        for (int n = 0; n < 4; n++)
#pragma unroll
            for (int j = 0; j < 4; j++) c[m][n][j] = 0.f;

    for (int kt = 0; kt < ksteps; kt++) {
        int k0 = kt * 32;
#pragma unroll
        for (int i = 0; i < 4; i++) {
            int q = tid + 256 * i;
            int e = q >> 5, k = q & 31;
            As[e][k] = f2tff(hin[(size_t)(nb + e) * HID + k0 + k]);
        }
#pragma unroll
        for (int i = 0; i < 32; i++) {
            int q = tid + 256 * i;
            int k = q >> 8, o = q & 255;
            Ws[k][o] = f2tff(wself[(size_t)(k0 + k) * HID + o]);
        }
        __syncthreads();
        int lr = lane >> 2, lc = lane & 3;
#pragma unroll
        for (int ks = 0; ks < 4; ks++) {
            int kk = ks * 8;
            unsigned a[2][4];
#pragma unroll
            for (int m = 0; m < 2; m++) {
                int r = m * 16 + lr;
                a[m][0] = __float_as_uint(As[r][kk + lc]);
                a[m][1] = __float_as_uint(As[r + 8][kk + lc]);
                a[m][2] = __float_as_uint(As[r][kk + 4 + lc]);
                a[m][3] = __float_as_uint(As[r + 8][kk + 4 + lc]);
            }
#pragma unroll
            for (int n = 0; n < 4; n++) {
                int nc = n0 + n * 8 + lr;
                unsigned b0 = __float_as_uint(Ws[kk + lc][nc]);
                unsigned b1 = __float_as_uint(Ws[kk + 4 + lc][nc]);
#pragma unroll
                for (int m = 0; m < 2; m++)
                    mma_tf32(c[m][n], a[m][0], a[m][1], a[m][2], a[m][3], b0, b1);
            }
        }
        __syncthreads();
    }
    int g = lane >> 2, cc = 2 * (lane & 3);
#pragma unroll
    for (int m = 0; m < 2; m++) {
        int row0 = nb + m * 16 + g;
        int row1 = row0 + 8;
#pragma unroll
        for (int n = 0; n < 4; n++) {
            int col = n0 + n * 8 + cc;
            float2 g0 = *(const float2*)&g_agg[(size_t)row0 * HID + col];
            float2 g1 = *(const float2*)&g_agg[(size_t)row1 * HID + col];
            float b0 = __ldg(&bself[col]), b1 = __ldg(&bself[col + 1]);
            float2 r0, r1;
            r0.x = fmaxf(c[m][n][0] + b0 + g0.x, 0.f);
            r0.y = fmaxf(c[m][n][1] + b1 + g0.y, 0.f);
            r1.x = fmaxf(c[m][n][2] + b0 + g1.x, 0.f);
            r1.y = fmaxf(c[m][n][3] + b1 + g1.y, 0.f);
            *(float2*)&hout[(size_t)row0 * HID + col] = r0;
            *(float2*)&hout[(size_t)row1 * HID + col] = r1;
        }
    }
}

// ============================================================
// Valence damping
// ============================================================
__global__ void k_damp(float* __restrict__ out_h, float* __restrict__ out_viol)
{
    int idx = blockIdx.x * 256 + threadIdx.x;
    int n = idx >> 6;
    float viol = fmaxf(g_deg[n] - (float)g_pv[n], 0.f);
    float s = 1.f / (1.f + viol);
    float4 v = ((const float4*)g_h1)[idx];
    v.x *= s; v.y *= s; v.z *= s; v.w *= s;
    ((float4*)out_h)[idx] = v;
    if (idx < NN)
        out_viol[idx] = fmaxf(g_deg[idx] - (float)g_pv[idx], 0.f);
}

// ============================================================
// Bond head: stage1 via tf32 MMA (K=512 + rank-2 pv), stages 2-3 SIMT
// ============================================================
__global__ __launch_bounds__(256) void k_bc(const float* __restrict__ hfin,
        const float* __restrict__ w1, const float* __restrict__ b1,
        const float* __restrict__ w2, const float* __restrict__ b2,
        const float* __restrict__ w3, const float* __restrict__ b3,
        const int* __restrict__ edge_index, float* __restrict__ out_bl)
{
    __shared__ float As[32][36];
    __shared__ float Ws[32][136];
    __shared__ float T1[32][129];
    __shared__ float T2[32][65];
    __shared__ int s_row[32], s_col[32], s_atr[32], s_atc[32];
    __shared__ float s_pvr[32], s_pvc[32];
    int tid = threadIdx.x;
    int eb = blockIdx.x * 32;
    if (tid < 32) {
        int e = eb + tid;
        int r = edge_index[e], c = edge_index[NE + e];
        s_row[tid] = r; s_col[tid] = c;
        s_pvr[tid] = (float)g_pv[r]; s_pvc[tid] = (float)g_pv[c];
        s_atr[tid] = g_atype[r];     s_atc[tid] = g_atype[c];
    }
    __syncthreads();

    // ---- stage 1: [32 x 128], K=512 via MMA; warp w owns cols [w*16, w*16+16)
    int warp = tid >> 5, lane = tid & 31;
    int n0 = warp * 16;
    float c[2][2][4];
#pragma unroll
    for (int m = 0; m < 2; m++)
#pragma unroll
        for (int n = 0; n < 2; n++)
#pragma unroll
            for (int j = 0; j < 4; j++) c[m][n][j] = 0.f;

    for (int kt = 0; kt < 16; kt++) {
        int k0 = kt * 32;
#pragma unroll
        for (int i = 0; i < 4; i++) {
            int q = tid + 256 * i;
            int e = q >> 5, k = q & 31;
            int kk = k0 + k;
            float v = (kk < 256) ? hfin[(size_t)s_row[e] * HID + kk]
                                 : hfin[(size_t)s_col[e] * HID + kk - 256];
            As[e][k] = f2tff(v);
        }
#pragma unroll
        for (int i = 0; i < 16; i++) {
            int q = tid + 256 * i;
            int k = q >> 7, o = q & 127;
            Ws[k][o] = f2tff(w1[(size_t)(k0 + k) * 128 + o]);
        }
        __syncthreads();
        int lr = lane >> 2, lc = lane & 3;
#pragma unroll
        for (int ks = 0; ks < 4; ks++) {
            int kk = ks * 8;
            unsigned a[2][4];
#pragma unroll
            for (int m = 0; m < 2; m++) {
                int r = m * 16 + lr;
                a[m][0] = __float_as_uint(As[r][kk + lc]);
                a[m][1] = __float_as_uint(As[r + 8][kk + lc]);
                a[m][2] = __float_as_uint(As[r][kk + 4 + lc]);
                a[m][3] = __float_as_uint(As[r + 8][kk + 4 + lc]);
            }
#pragma unroll
            for (int n = 0; n < 2; n++) {
                int nc = n0 + n * 8 + lr;
                unsigned b0 = __float_as_uint(Ws[kk + lc][nc]);
                unsigned b1 = __float_as_uint(Ws[kk + 4 + lc][nc]);
#pragma unroll
                for (int m = 0; m < 2; m++)
                    mma_tf32(c[m][n], a[m][0], a[m][1], a[m][2], a[m][3], b0, b1);
            }
        }
        __syncthreads();
    }
    {
        int g = lane >> 2, cc = 2 * (lane & 3);
#pragma unroll
        for (int m = 0; m < 2; m++) {
            int r0 = m * 16 + g, r1 = r0 + 8;
#pragma unroll
            for (int n = 0; n < 2; n++) {
                int col = n0 + n * 8 + cc;
#pragma unroll
                for (int j = 0; j < 2; j++) {
                    int o = col + j;
                    float wpr = __ldg(&w1[512 * 128 + o]);
                    float wpc = __ldg(&w1[513 * 128 + o]);
                    float bb = __ldg(&b1[o]);
                    T1[r0][o] = fmaxf(c[m][n][j]     + s_pvr[r0] * wpr + s_pvc[r0] * wpc + bb, 0.f);
                    T1[r1][o] = fmaxf(c[m][n][j + 2] + s_pvr[r1] * wpr + s_pvc[r1] * wpc + bb, 0.f);
                }
            }
        }
    }
    __syncthreads();

    // ---- stage 2: [32 x 64], K=128 (SIMT) ----
    float acc2[2][4];
#pragma unroll
    for (int i = 0; i < 2; i++)
#pragma unroll
        for (int j = 0; j < 4; j++) acc2[i][j] = 0.f;
    const int tx2 = tid & 15, ty2 = tid >> 4;
    for (int kt = 0; kt < 4; kt++) {
        int k0 = kt * 32;
#pragma unroll
        for (int i = 0; i < 8; i++) {
            int q = tid + 256 * i;
            int k = q >> 6, o = q & 63;
            Ws[k][o] = w2[(size_t)(k0 + k) * 64 + o];
        }
        __syncthreads();
#pragma unroll
        for (int kk = 0; kk < 32; kk++) {
            float a0 = T1[ty2 * 2][k0 + kk];
            float a1 = T1[ty2 * 2 + 1][k0 + kk];
            float4 w = *(const float4*)&Ws[kk][tx2 * 4];
            acc2[0][0] += a0 * w.x; acc2[0][1] += a0 * w.y;
            acc2[0][2] += a0 * w.z; acc2[0][3] += a0 * w.w;
            acc2[1][0] += a1 * w.x; acc2[1][1] += a1 * w.y;
            acc2[1][2] += a1 * w.z; acc2[1][3] += a1 * w.w;
        }
        __syncthreads();
    }
#pragma unroll
    for (int i = 0; i < 2; i++) {
        int e = ty2 * 2 + i;
#pragma unroll
        for (int j = 0; j < 4; j++) {
            int o = tx2 * 4 + j;
            T2[e][o] = fmaxf(acc2[i][j] + __ldg(&b2[o]), 0.f);
        }
    }
    __syncthreads();

    // ---- stage 3: [32 x 4], K=64, + chemical penalties ----
    if (tid < 128) {
        int e = tid >> 2, o = tid & 3;
        float s = __ldg(&b3[o]);
#pragma unroll
        for (int k = 0; k < 64; k++) s += T2[e][k] * __ldg(&w3[k * 4 + o]);
        int ar = s_atr[e], ac = s_atc[e];
        float pr = s_pvr[e], pc = s_pvc[e];
        bool hal = (ar == 4) || (ar == 5) || (ac == 4) || (ac == 5);
        bool l1 = (pr <= 1.f) || (pc <= 1.f);
        bool l2 = (pr <= 2.f) || (pc <= 2.f);
        float pen = 0.f;
        if (o >= 1) { if (hal) pen -= 100.f; if (l1) pen -= 50.f; }
        if (o == 2) { if (l2) pen -= 50.f; }
        out_bl[(size_t)(eb + e) * 4 + o] = s + pen;
    }
}

// ============================================================
// Chem head (SIMT; small)
// ============================================================
__global__ __launch_bounds__(256) void k_cp(const float* __restrict__ hfin,
        const float* __restrict__ w1, const float* __restrict__ b1,
        const float* __restrict__ w2, const float* __restrict__ b2,
        float* __restrict__ out_cp)
{
    __shared__ float As[32][33];
    __shared__ float Ws[32][128];
    __shared__ float T1[32][129];
    int tid = threadIdx.x;
    int nb = blockIdx.x * 32;
    float acc[4][4];
#pragma unroll
    for (int i = 0; i < 4; i++)
#pragma unroll
        for (int j = 0; j < 4; j++) acc[i][j] = 0.f;
    const int tx = tid & 31, ty = tid >> 5;
    for (int kt = 0; kt < 8; kt++) {
        int k0 = kt * 32;
#pragma unroll
        for (int i = 0; i < 4; i++) {
            int q = tid + 256 * i;
            int e = q >> 5, k = q & 31;
            As[e][k] = hfin[(size_t)(nb + e) * HID + k0 + k];
        }
#pragma unroll
        for (int i = 0; i < 16; i++) {
            int q = tid + 256 * i;
            int k = q >> 7, o = q & 127;
            Ws[k][o] = w1[(size_t)(k0 + k) * 128 + o];
        }
        __syncthreads();
#pragma unroll
        for (int kk = 0; kk < 32; kk++) {
            float a[4];
#pragma unroll
            for (int i = 0; i < 4; i++) a[i] = As[ty * 4 + i][kk];
            float4 w = *(const float4*)&Ws[kk][tx * 4];
#pragma unroll
            for (int i = 0; i < 4; i++) {
                acc[i][0] += a[i] * w.x; acc[i][1] += a[i] * w.y;
                acc[i][2] += a[i] * w.z; acc[i][3] += a[i] * w.w;
            }
        }
        __syncthreads();
    }
#pragma unroll
    for (int i = 0; i < 4; i++) {
        int e = ty * 4 + i;
#pragma unroll
        for (int j = 0; j < 4; j++) {
            int o = tx * 4 + j;
            T1[e][o] = fmaxf(acc[i][j] + __ldg(&b1[o]), 0.f);
        }
    }
    __syncthreads();

    float acc2[4] = {0.f, 0.f, 0.f, 0.f};
    const int tx2 = tid & 7, ty2 = tid >> 3;
    for (int kt = 0; kt < 4; kt++) {
        int k0 = kt * 32;
#pragma unroll
        for (int i = 0; i < 4; i++) {
            int q = tid + 256 * i;
            int k = q >> 5, o = q & 31;
            Ws[k][o] = w2[(size_t)(k0 + k) * 32 + o];
        }
        __syncthreads();
#pragma unroll
        for (int kk = 0; kk < 32; kk++) {
            float a = T1[ty2][k0 + kk];
            float4 w = *(const float4*)&Ws[kk][tx2 * 4];
            acc2[0] += a * w.x; acc2[1] += a * w.y;
            acc2[2] += a * w.z; acc2[3] += a * w.w;
        }
        __syncthreads();
    }
#pragma unroll
    for (int j = 0; j < 4; j++) {
        int o = tx2 * 4 + j;
        out_cp[(size_t)(nb + ty2) * 32 + o] = acc2[j] + __ldg(&b2[o]);
    }
}

// ============================================================
extern "C" void kernel_launch(void* const* d_in, const int* in_sizes, int n_in,
                              void* d_out, int out_size)
{
    (void)in_sizes; (void)n_in; (void)out_size;
    const float* x         = (const float*)d_in[0];
    const float* edge_attr = (const float*)d_in[1];
    const float* atom_emb  = (const float*)d_in[2];
    const float* bond_emb  = (const float*)d_in[3];
    const float* vp_w1     = (const float*)d_in[4];
    const float* vp_b1     = (const float*)d_in[5];
    const float* vp_w2     = (const float*)d_in[6];
    const float* vp_b2     = (const float*)d_in[7];
    const float* gnn_wself = (const float*)d_in[8];
    const float* gnn_bself = (const float*)d_in[9];
    const float* gnn_wmsg  = (const float*)d_in[10];
    const float* gnn_bmsg  = (const float*)d_in[11];
    const float* bc_w1     = (const float*)d_in[12];
    const float* bc_b1     = (const float*)d_in[13];
    const float* bc_w2     = (const float*)d_in[14];
    const float* bc_b2     = (const float*)d_in[15];
    const float* bc_w3     = (const float*)d_in[16];
    const float* bc_b3     = (const float*)d_in[17];
    const float* cp_w1     = (const float*)d_in[18];
    const float* cp_b1     = (const float*)d_in[19];
    const float* cp_w2     = (const float*)d_in[20];
    const float* cp_b2     = (const float*)d_in[21];
    const int* edge_index  = (const int*)d_in[22];

    float* out      = (float*)d_out;
    float* out_h    = out;                                 // [N,256]
    float* out_cp   = out_h    + (size_t)NN * HID;         // [N,32]
    float* out_vlog = out_cp   + (size_t)NN * 32;          // [N,8]
    float* out_bl   = out_vlog + (size_t)NN * 8;           // [E,4]
    float* out_viol = out_bl   + (size_t)NE * 4;           // [N]

    k_type_pred<<<1, 32>>>(atom_emb, vp_w1, vp_b1, vp_w2, vp_b2);
    k_fold<<<15, 256>>>(gnn_wmsg, gnn_bmsg, bond_emb);
    k_node_init<<<(NN * 32 + 255) / 256, 256>>>(x, atom_emb, out_vlog);
    k_degree<<<(NE + 255) / 256, 256>>>(edge_index);

    int ping = 0;
    for (int l = 0; l < 3; l++) {
        int ksteps = (l == 0) ? 3 : 8;   // layer-0 h has only 72 nonzero cols
        k_zero_agg<<<(NN * HID / 4) / 256, 256>>>();
        k_msg<<<NE / 32, 256>>>(ping, ksteps, l,
                                gnn_wmsg + (size_t)l * 320 * HID,
                                edge_attr, edge_index);
        k_self<<<NN / 32, 256>>>(ping, ksteps,
                                 gnn_wself + (size_t)l * HID * HID,
                                 gnn_bself + l * HID);
        ping ^= 1;
    }
    // final h in g_h1
    k_damp<<<(NN * HID / 4) / 256, 256>>>(out_h, out_viol);
    k_bc<<<NE / 32, 256>>>(out_h, bc_w1, bc_b1, bc_w2, bc_b2, bc_w3, bc_b3,
                           edge_index, out_bl);
    k_cp<<<NN / 32, 256>>>(out_h, cp_w1, cp_b1, cp_w2, cp_b2, out_cp);
}